// round 6
// baseline (speedup 1.0000x reference)
#include <cuda_runtime.h>
#include <cstdint>
#include <math.h>

#define D_DIM   1024
#define T_DIM   50
#define STRIDEQ 10
#define NUM_POS 16
#define MAX_B   4096
#define MAX_KP  13108   /* ceil(131072/10) */
#define CHUNK   2048
#define AG      4       /* anchors per select block */
#define NWMAX   416     /* ceil(13108/32)=410, padded */

// ---- device scratch (static; no allocations allowed) ----
__device__ ulonglong2 g_q[MAX_KP];
__device__ ulonglong2 g_a[MAX_B];
__device__ int        g_key[MAX_B];
__device__ int        g_order[MAX_B];
__device__ int        g_sel[MAX_B * NUM_POS];
__device__ int        g_cnt[MAX_B];
__device__ float      g_per[MAX_B];
__device__ unsigned   g_counter;

// ------------------------------------------------------------------
// Kernel 1: pack labels; anchors also get a density-proxy key.
// ------------------------------------------------------------------
__global__ void prep_labels(const int* __restrict__ xlab,
                            const int* __restrict__ qlab,
                            int B, int Kp) {
    if (blockIdx.x == 0 && threadIdx.x == 0) g_counter = 0;
    int warp = (blockIdx.x * blockDim.x + threadIdx.x) >> 5;
    int lane = threadIdx.x & 31;
    if (warp >= Kp + B) return;

    const int* lp = (warp < Kp)
        ? qlab + (long long)warp * STRIDEQ * (T_DIM * 2)
        : xlab + (long long)(warp - Kp) * (T_DIM * 2);

    int2 va = ((const int2*)lp)[lane];
    int l0b = 0, l1b = 0;
    if (32 + lane < T_DIM) {
        int2 vb = ((const int2*)lp)[32 + lane];
        l0b = vb.x; l1b = vb.y;
    }
    unsigned b0lo = __ballot_sync(0xffffffffu, va.x != 0);
    unsigned b1lo = __ballot_sync(0xffffffffu, va.y != 0);
    unsigned b0hi = __ballot_sync(0xffffffffu, l0b != 0);
    unsigned b1hi = __ballot_sync(0xffffffffu, l1b != 0);
    if (lane == 0) {
        ulonglong2 v;
        v.x = (unsigned long long)b0lo | ((unsigned long long)b0hi << 32);
        v.y = (unsigned long long)b1lo | ((unsigned long long)b1hi << 32);
        if (warp < Kp) g_q[warp] = v;
        else {
            int b = warp - Kp;
            g_a[b] = v;
            // density proxy: E[lab-sim contribution] per anchor state
            float mu = 0.4268f * (float)__popcll(v.x ^ v.y)
                     + 0.6036f * (float)__popcll(v.x & v.y);
            int key = (int)(mu * 8.0f);
            g_key[b] = key > 255 ? 255 : (key < 0 ? 0 : key);
        }
    }
}

// ------------------------------------------------------------------
// Kernel 2: counting sort of anchors by density key (single block).
// ------------------------------------------------------------------
__global__ void __launch_bounds__(256)
sort_anchors(int B) {
    __shared__ int hist[256];
    __shared__ int off[256];
    int tid = threadIdx.x;
    hist[tid] = 0;
    __syncthreads();
    for (int i = tid; i < B; i += 256) atomicAdd(&hist[g_key[i]], 1);
    __syncthreads();
    if (tid == 0) {
        int acc = 0;
        for (int i = 0; i < 256; i++) { off[i] = acc; acc += hist[i]; }
    }
    __syncthreads();
    for (int i = tid; i < B; i += 256) {
        int p = atomicAdd(&off[g_key[i]], 1);
        g_order[p] = i;
    }
}

// ------------------------------------------------------------------
// Predicate (exact fp32, validated R1-R5).
// ------------------------------------------------------------------
__device__ __forceinline__ bool pair_pred(
    unsigned long long a0, unsigned long long a1,
    unsigned long long da, unsigned long long xa,
    unsigned long long q0, unsigned long long q1,
    float c, float d2) {
    unsigned long long dq = q0 & q1;
    unsigned long long xk = q0 ^ q1;
    unsigned long long m1  = (xa & xk) & ~(a0 ^ q0);
    unsigned long long mc  = (da & xk) | (xa & dq);
    unsigned long long mdd = da & dq;
    float s = (float)__popcll(m1)
            + (float)__popcll(mc)  * c
            + (float)__popcll(mdd) * d2;
    return s >= 25.0f;
}

// ------------------------------------------------------------------
// Kernel 3: grouped adaptive selection. Block (256 thr) handles AG=4
// density-matched anchors; each g_q load serves 4 predicates.
// ------------------------------------------------------------------
__global__ void __launch_bounds__(256)
select_kernel(int B, int Kp) {
    __shared__ unsigned s_words[AG][NWMAX];
    __shared__ int      s_tot[AG];
    int tid  = threadIdx.x;
    int lane = tid & 31;
    int w    = tid >> 5;
    int grp  = blockIdx.x * AG;

    int bidx[AG];
    unsigned long long a0[AG], a1[AG], da[AG], xa[AG];
#pragma unroll
    for (int j = 0; j < AG; j++) {
        int b = g_order[grp + j];
        bidx[j] = b;
        ulonglong2 av = g_a[b];
        a0[j] = av.x; a1[j] = av.y;
        da[j] = av.x & av.y; xa[j] = av.x ^ av.y;
    }
    float c  = 1.0f / (sqrtf(2.0f) + 1e-8f);
    float cc = c * c;
    float d2 = cc + cc;

    if (tid < AG) s_tot[tid] = 0;
    __syncthreads();

    int chunk_end = 0;
#pragma unroll 1
    for (int base = 0; base < Kp; base += CHUNK) {
        int lim   = (base + CHUNK < Kp) ? base + CHUNK : Kp;
        int nIter = (lim - base + 255) >> 8;
#pragma unroll 1
        for (int i = 0; i < nIter; i++) {
            int k = base + i * 256 + tid;
            bool inb = (k < lim);
            unsigned long long q0 = 0, q1 = 0;
            if (inb) { ulonglong2 qv = g_q[k]; q0 = qv.x; q1 = qv.y; }
#pragma unroll
            for (int j = 0; j < AG; j++) {
                bool pred = inb && pair_pred(a0[j], a1[j], da[j], xa[j], q0, q1, c, d2);
                unsigned m = __ballot_sync(0xffffffffu, pred);
                if (lane == 0) s_words[j][(base >> 5) + i * 8 + w] = m;
            }
        }
        __syncthreads();
        // count this chunk's words: warp j counts anchor j
        if (w < AG) {
            int w0 = base >> 5;
            int nw = nIter * 8;             // <= 64
            int cw = (lane < nw) ? __popc(s_words[w][w0 + lane]) : 0;
            if (nw > 32 && lane + 32 < nw) cw += __popc(s_words[w][w0 + lane + 32]);
#pragma unroll
            for (int o = 16; o; o >>= 1) cw += __shfl_xor_sync(0xffffffffu, cw, o);
            if (lane == 0) s_tot[w] += cw;
        }
        __syncthreads();
        chunk_end = lim;
        if (s_tot[0] >= NUM_POS && s_tot[1] >= NUM_POS &&
            s_tot[2] >= NUM_POS && s_tot[3] >= NUM_POS) break;
    }

    // ---- ordered extraction: warp j extracts anchor j's first <=16 ----
    if (w < AG) {
        int b = bidx[w];
        int nwords = (chunk_end + 31) >> 5;
        int run = 0;
        for (int g = 0; g * 32 < nwords && run < NUM_POS; g++) {
            int wi = g * 32 + lane;
            unsigned word = (wi < nwords) ? s_words[w][wi] : 0u;
            int my = __popc(word);
            int pre = my;
#pragma unroll
            for (int o = 1; o < 32; o <<= 1) {
                int v = __shfl_up_sync(0xffffffffu, pre, o);
                if (lane >= o) pre += v;
            }
            int gtot = __shfl_sync(0xffffffffu, pre, 31);
            int rank = run + pre - my;
            while (word && rank < NUM_POS) {
                int bit = __ffs(word) - 1;
                word &= word - 1;
                g_sel[b * NUM_POS + rank++] = wi * 32 + bit;
            }
            run += gtot;
        }
        if (lane == 0) {
            int t = s_tot[w];
            g_cnt[b] = (t < NUM_POS) ? t : NUM_POS;
        }
    }
}

// ------------------------------------------------------------------
// Kernel 4: per anchor, 16 gathered dots (norms fused) + loss +
// last-block deterministic mean. (Validated numeric path.)
// ------------------------------------------------------------------
__global__ void __launch_bounds__(512)
loss_kernel(const float* __restrict__ xq, const float* __restrict__ qf,
            float* __restrict__ out, int B) {
    __shared__ float  s_anchor[D_DIM];
    __shared__ float  s_ssq[256];
    __shared__ float  s_loss[NUM_POS];
    __shared__ int    s_last;
    __shared__ double s_red[512];

    int b    = blockIdx.x;
    int tid  = threadIdx.x;
    int w    = tid >> 5;
    int lane = tid & 31;

    if (tid >= 256) {
        int i = tid - 256;
        float4 v = ((const float4*)(xq + (long long)b * D_DIM))[i];
        ((float4*)s_anchor)[i] = v;
        s_ssq[i] = v.x * v.x + v.y * v.y + v.z * v.z + v.w * v.w;
    }
    __syncthreads();

    int cnt = g_cnt[b];
    float loss = 0.f;
    if (w < cnt) {
        int kp = g_sel[b * NUM_POS + w];
        const float4* pk = (const float4*)(qf + (long long)kp * STRIDEQ * D_DIM);
        const float4* pa = (const float4*)s_anchor;
        float dot = 0.f, kss = 0.f;
#pragma unroll
        for (int i = 0; i < D_DIM / 4 / 32; i++) {
            float4 a  = pa[lane + i * 32];
            float4 kk = pk[lane + i * 32];
            dot += a.x * kk.x + a.y * kk.y + a.z * kk.z + a.w * kk.w;
            kss += kk.x * kk.x + kk.y * kk.y + kk.z * kk.z + kk.w * kk.w;
        }
#pragma unroll
        for (int o = 16; o; o >>= 1) {
            dot += __shfl_xor_sync(0xffffffffu, dot, o);
            kss += __shfl_xor_sync(0xffffffffu, kss, o);
        }
        float qss = s_ssq[lane] + s_ssq[lane + 32] + s_ssq[lane + 64]
                  + s_ssq[lane + 96] + s_ssq[lane + 128] + s_ssq[lane + 160]
                  + s_ssq[lane + 192] + s_ssq[lane + 224];
#pragma unroll
        for (int o = 16; o; o >>= 1) qss += __shfl_xor_sync(0xffffffffu, qss, o);

        float inv_q = 1.0f / (sqrtf(qss) + 1e-8f);
        float inv_k = 1.0f / (sqrtf(kss) + 1e-8f);
        float s = dot * inv_q * inv_k * 2.0f;     // / TEMPERATURE(0.5)
        float z = -s;
        loss = fmaxf(z, 0.f) + log1pf(expf(-fabsf(z)));
    }
    if (lane == 0 && w < NUM_POS) s_loss[w] = loss;
    __syncthreads();

    if (tid == 0) {
        float sum = 0.f;
#pragma unroll
        for (int i = 0; i < NUM_POS; i++) sum += (i < cnt) ? s_loss[i] : 0.f;
        g_per[b] = (cnt > 0) ? (sum / (float)cnt) : 0.f;
        __threadfence();
        unsigned t = atomicAdd(&g_counter, 1u);
        s_last = (t == (unsigned)(gridDim.x - 1)) ? 1 : 0;
    }
    __syncthreads();

    if (s_last) {
        double acc = 0.0;
        for (int i = tid; i < B; i += 512) acc += (double)g_per[i];
        s_red[tid] = acc;
        __syncthreads();
        for (int s = 256; s; s >>= 1) {
            if (tid < s) s_red[tid] += s_red[tid + s];
            __syncthreads();
        }
        if (tid == 0) out[0] = (float)(s_red[0] / (double)B);
    }
}

extern "C" void kernel_launch(void* const* d_in, const int* in_sizes, int n_in,
                              void* d_out, int out_size) {
    const float* xq   = (const float*)d_in[0];
    const int*   xlab = (const int*)  d_in[1];
    const float* qf   = (const float*)d_in[2];
    const int*   qlab = (const int*)  d_in[3];

    int B  = in_sizes[0] / D_DIM;                 // 4096
    int K  = in_sizes[2] / D_DIM;                 // 131072
    int Kp = (K + STRIDEQ - 1) / STRIDEQ;         // 13108

    int warps  = Kp + B;
    int blocks = (warps * 32 + 255) / 256;
    prep_labels  <<<blocks, 256>>>(xlab, qlab, B, Kp);
    sort_anchors <<<1, 256>>>(B);
    select_kernel<<<B / AG, 256>>>(B, Kp);
    loss_kernel  <<<B, 512>>>(xq, qf, (float*)d_out, B);
}